// round 17
// baseline (speedup 1.0000x reference)
#include <cuda_runtime.h>
#include <math.h>

// StatisticalFeatureExtractor: (B=64, C=16, T=65536) fp32 -> (B, C, 17) fp32
// One CTA (512 thr) per TWO rows, 2 CTAs/SM. Three phases per CTA:
//   A: rowA minimal pass-1 (S1,min,max,zc)            [DRAM]
//   B: rowA heavy stats (L2) + rowB minimal pass-1    [L2 + DRAM overlapped]
//   C: rowB heavy stats                               [L2]
// Branch-free sign logic; shfl cross-chunk pairs; 511 warp-span boundary
// pairs per row in cleanup steps; double finalization.

#define TLEN    65536
#define CHUNKS  (TLEN / 4)
#define THREADS 512
#define NWARP   (THREADS / 32)
#define EPSV    1e-8

typedef unsigned long long u64;

__device__ __forceinline__ u64 pk2(float x, float y) {
    u64 r; asm("mov.b64 %0, {%1, %2};" : "=l"(r) : "f"(x), "f"(y)); return r;
}
__device__ __forceinline__ void up2(u64 a, float& x, float& y) {
    asm("mov.b64 {%0, %1}, %2;" : "=f"(x), "=f"(y) : "l"(a));
}
__device__ __forceinline__ u64 add2(u64 a, u64 b) {
    u64 r; asm("add.rn.f32x2 %0, %1, %2;" : "=l"(r) : "l"(a), "l"(b)); return r;
}
__device__ __forceinline__ u64 mul2(u64 a, u64 b) {
    u64 r; asm("mul.rn.f32x2 %0, %1, %2;" : "=l"(r) : "l"(a), "l"(b)); return r;
}
__device__ __forceinline__ u64 fma2(u64 a, u64 b, u64 c) {
    u64 r; asm("fma.rn.f32x2 %0, %1, %2, %3;" : "=l"(r) : "l"(a), "l"(b), "l"(c)); return r;
}
__device__ __forceinline__ float sqrt_approx(float v) {
    float r; asm("sqrt.approx.f32 %0, %1;" : "=f"(r) : "f"(v)); return r;
}
__device__ __forceinline__ float hsum2(u64 a) { float x, y; up2(a, x, y); return x + y; }

__device__ __forceinline__ float warp_sum(float v) {
#pragma unroll
    for (int o = 16; o; o >>= 1) v += __shfl_xor_sync(0xffffffffu, v, o);
    return v;
}
__device__ __forceinline__ int warp_sumi(int v) {
#pragma unroll
    for (int o = 16; o; o >>= 1) v += __shfl_xor_sync(0xffffffffu, v, o);
    return v;
}
__device__ __forceinline__ float warp_max(float v) {
#pragma unroll
    for (int o = 16; o; o >>= 1) v = fmaxf(v, __shfl_xor_sync(0xffffffffu, v, o));
    return v;
}
__device__ __forceinline__ float warp_min(float v) {
#pragma unroll
    for (int o = 16; o; o >>= 1) v = fminf(v, __shfl_xor_sync(0xffffffffu, v, o));
    return v;
}

// final 17-feature math (tid 0 only), shared by both rows
__device__ __forceinline__ void finalize_row(
    float* o, double S1, double S2, double Sa, double Sq,
    double pk, double pkn, int zct, int mct,
    double D2, double D3, double D4)
{
    const double Td   = (double)TLEN;
    const double invT = 1.0 / Td;
    double meanv     = S1 * invT;
    double var       = D2 / (Td - 1.0);
    double stdv      = sqrt(var);
    double sq_mean   = S2 * invT;
    double rms       = sqrt(sq_mean);
    double ptp       = pk - pkn;
    double abs_peak  = fabs(pk);
    double crest     = abs_peak / (rms + EPSV);
    double mean_abs  = Sa * invT;
    double shape     = rms / (mean_abs + EPSV);
    double impulse   = abs_peak / (mean_abs + EPSV);
    double sqrt_mean = Sq * invT;
    double clearance = abs_peak / (sqrt_mean * sqrt_mean + EPSV);
    double skew      = (D3 * invT) / (stdv * stdv * stdv + EPSV);
    double kurt      = (D4 * invT) / (var * var + EPSV) - 3.0;
    double zcr       = (double)zct / (Td - 1.0);
    double mcr       = (double)mct / (Td - 1.0);
    double margin    = abs_peak / (sqrt_mean + EPSV);
    double energy    = S2;

    o[0]  = (float)meanv;  o[1]  = (float)stdv;   o[2]  = (float)var;
    o[3]  = (float)rms;    o[4]  = (float)pk;     o[5]  = (float)pkn;
    o[6]  = (float)ptp;    o[7]  = (float)crest;  o[8]  = (float)shape;
    o[9]  = (float)impulse; o[10] = (float)clearance; o[11] = (float)skew;
    o[12] = (float)kurt;   o[13] = (float)zcr;    o[14] = (float)mcr;
    o[15] = (float)margin; o[16] = (float)energy;
}

__global__ __launch_bounds__(THREADS, 2)
void stat_feat_kernel(const float* __restrict__ x, float* __restrict__ out) {
    const int rowA = 2 * blockIdx.x;
    const int rowB = rowA + 1;
    const float* __restrict__ xa = x + (size_t)rowA * TLEN;
    const float* __restrict__ xb = x + (size_t)rowB * TLEN;
    const float4* __restrict__ xa4 = reinterpret_cast<const float4*>(xa);
    const float4* __restrict__ xb4 = reinterpret_cast<const float4*>(xb);

    const int tid  = threadIdx.x;
    const int wid  = tid >> 5;
    const int lane = tid & 31;
    const unsigned vmask = (lane != 31) ? 1u : 0u;

    __shared__ float  w_f[9][NWARP];
    __shared__ int    w_k[3][NWARP];
    __shared__ double sA_S1, sB_S1;
    __shared__ float  s_meanA, s_meanB;
    __shared__ float  sA_pk, sA_pkn, sB_pk, sB_pkn;
    __shared__ int    sA_zc, sB_zc;

    const u64 ABSM = 0x7fffffff7fffffffULL;

    // ================= Phase A: rowA minimal pass-1 (DRAM) =================
    {
        u64 s1p = 0;
        float mx = -INFINITY, mn = INFINITY;
        int zc = 0;
#pragma unroll 8
        for (int k = tid; k < CHUNKS; k += THREADS) {
            float4 v = xa4[k];
            u64 plo = pk2(v.x, v.y), phi = pk2(v.z, v.w);
            s1p = add2(s1p, add2(plo, phi));
            mx = fmaxf(mx, fmaxf(fmaxf(v.x, v.y), fmaxf(v.z, v.w)));
            mn = fminf(mn, fminf(fminf(v.x, v.y), fminf(v.z, v.w)));
            unsigned u0 = __float_as_uint(v.x), u1 = __float_as_uint(v.y);
            unsigned u2 = __float_as_uint(v.z), u3 = __float_as_uint(v.w);
            unsigned nu0 = __shfl_down_sync(0xffffffffu, u0, 1);
            zc += (int)(((u0 ^ u1) >> 31) + ((u1 ^ u2) >> 31) + ((u2 ^ u3) >> 31)
                        + (((u3 ^ nu0) >> 31) & vmask));
        }
        float s1 = hsum2(s1p);
        s1 = warp_sum(s1); mx = warp_max(mx); mn = warp_min(mn); zc = warp_sumi(zc);
        if (lane == 0) { w_f[0][wid] = s1; w_f[1][wid] = mx; w_f[2][wid] = mn; w_k[0][wid] = zc; }
    }
    __syncthreads();
    if (tid == 0) {
        double S1 = 0.0;
        float rmx = -INFINITY, rmn = INFINITY;
        int rzc = 0;
        for (int i = 0; i < NWARP; i++) {
            S1 += (double)w_f[0][i];
            rmx = fmaxf(rmx, w_f[1][i]); rmn = fminf(rmn, w_f[2][i]);
            rzc += w_k[0][i];
        }
        sA_S1 = S1; sA_pk = rmx; sA_pkn = rmn; sA_zc = rzc;
        s_meanA = (float)(S1 * (1.0 / (double)TLEN));
    }
    __syncthreads();

    // ============ Phase B: rowA heavy (L2) + rowB minimal (DRAM) ============
    {
        const float meanA = s_meanA;
        const u64 nmA = pk2(-meanA, -meanA);
        u64 s2p = 0, sap = 0, d2p = 0, d3p = 0, d4p = 0;
        float sq0 = 0.f, sq1 = 0.f;
        int mc = 0;
        u64 s1pB = 0;
        float mxB = -INFINITY, mnB = INFINITY;
        int zcB = 0;

#pragma unroll 4
        for (int k = tid; k < CHUNKS; k += THREADS) {
            float4 va = xa4[k];     // L2 (just streamed in phase A)
            float4 vb = xb4[k];     // DRAM

            // --- rowA heavy ---
            u64 plo = pk2(va.x, va.y), phi = pk2(va.z, va.w);
            s2p = fma2(plo, plo, s2p);
            s2p = fma2(phi, phi, s2p);
            u64 alo = plo & ABSM, ahi = phi & ABSM;
            sap = add2(sap, add2(alo, ahi));
            float b0, b1, b2, b3;
            up2(alo, b0, b1); up2(ahi, b2, b3);
            sq0 += sqrt_approx(b0) + sqrt_approx(b1);
            sq1 += sqrt_approx(b2) + sqrt_approx(b3);
            u64 dlo = add2(plo, nmA), dhi = add2(phi, nmA);
            u64 tlo = mul2(dlo, dlo), thi = mul2(dhi, dhi);
            d2p = add2(d2p, add2(tlo, thi));
            d3p = fma2(tlo, dlo, d3p);
            d3p = fma2(thi, dhi, d3p);
            d4p = fma2(tlo, tlo, d4p);
            d4p = fma2(thi, thi, d4p);
            float d0, d1, d2v, d3v;
            up2(dlo, d0, d1); up2(dhi, d2v, d3v);
            unsigned c0 = __float_as_uint(d0), c1 = __float_as_uint(d1);
            unsigned c2 = __float_as_uint(d2v), c3 = __float_as_uint(d3v);
            unsigned nc0 = __shfl_down_sync(0xffffffffu, c0, 1);
            mc += (int)(((c0 ^ c1) >> 31) + ((c1 ^ c2) >> 31) + ((c2 ^ c3) >> 31)
                        + (((c3 ^ nc0) >> 31) & vmask));

            // --- rowB minimal ---
            u64 qlo = pk2(vb.x, vb.y), qhi = pk2(vb.z, vb.w);
            s1pB = add2(s1pB, add2(qlo, qhi));
            mxB = fmaxf(mxB, fmaxf(fmaxf(vb.x, vb.y), fmaxf(vb.z, vb.w)));
            mnB = fminf(mnB, fminf(fminf(vb.x, vb.y), fminf(vb.z, vb.w)));
            unsigned e0 = __float_as_uint(vb.x), e1 = __float_as_uint(vb.y);
            unsigned e2 = __float_as_uint(vb.z), e3 = __float_as_uint(vb.w);
            unsigned ne0 = __shfl_down_sync(0xffffffffu, e0, 1);
            zcB += (int)(((e0 ^ e1) >> 31) + ((e1 ^ e2) >> 31) + ((e2 ^ e3) >> 31)
                         + (((e3 ^ ne0) >> 31) & vmask));
        }

        // rowA cleanup: 511 warp-span boundary pairs (zcr & mcr), L2-hot
        int zceA = 0;
        if (tid < 511) {
            float a = __ldg(xa + 128 * tid + 127);
            float b = __ldg(xa + 128 * tid + 128);
            zceA = (int)((__float_as_uint(a) ^ __float_as_uint(b)) >> 31);
            float ca = a - meanA, cb = b - meanA;
            mc += (int)((__float_as_uint(ca) ^ __float_as_uint(cb)) >> 31);
        }

        float s2 = hsum2(s2p), sa = hsum2(sap), sqv = sq0 + sq1;
        float d2 = hsum2(d2p), d3 = hsum2(d3p), d4 = hsum2(d4p);
        float s1B = hsum2(s1pB);
        s2 = warp_sum(s2); sa = warp_sum(sa); sqv = warp_sum(sqv);
        d2 = warp_sum(d2); d3 = warp_sum(d3); d4 = warp_sum(d4);
        s1B = warp_sum(s1B); mxB = warp_max(mxB); mnB = warp_min(mnB);
        mc = warp_sumi(mc); zceA = warp_sumi(zceA); zcB = warp_sumi(zcB);
        if (lane == 0) {
            w_f[0][wid] = s2;  w_f[1][wid] = sa;  w_f[2][wid] = sqv;
            w_f[3][wid] = d2;  w_f[4][wid] = d3;  w_f[5][wid] = d4;
            w_f[6][wid] = s1B; w_f[7][wid] = mxB; w_f[8][wid] = mnB;
            w_k[0][wid] = mc;  w_k[1][wid] = zceA; w_k[2][wid] = zcB;
        }
    }
    __syncthreads();
    if (tid == 0) {
        double S2 = 0, Sa = 0, Sq = 0, D2 = 0, D3 = 0, D4 = 0, S1B = 0;
        float rmxB = -INFINITY, rmnB = INFINITY;
        int rmc = 0, rzceA = 0, rzcB = 0;
        for (int i = 0; i < NWARP; i++) {
            S2 += (double)w_f[0][i]; Sa += (double)w_f[1][i]; Sq += (double)w_f[2][i];
            D2 += (double)w_f[3][i]; D3 += (double)w_f[4][i]; D4 += (double)w_f[5][i];
            S1B += (double)w_f[6][i];
            rmxB = fmaxf(rmxB, w_f[7][i]); rmnB = fminf(rmnB, w_f[8][i]);
            rmc += w_k[0][i]; rzceA += w_k[1][i]; rzcB += w_k[2][i];
        }
        // finalize rowA
        finalize_row(out + (size_t)rowA * 17,
                     sA_S1, S2, Sa, Sq, (double)sA_pk, (double)sA_pkn,
                     sA_zc + rzceA, rmc, D2, D3, D4);
        // set up rowB
        sB_S1 = S1B; sB_pk = rmxB; sB_pkn = rmnB; sB_zc = rzcB;
        s_meanB = (float)(S1B * (1.0 / (double)TLEN));
    }
    __syncthreads();

    // ================= Phase C: rowB heavy stats (L2) =================
    {
        const float meanB = s_meanB;
        const u64 nmB = pk2(-meanB, -meanB);
        u64 s2p = 0, sap = 0, d2p = 0, d3p = 0, d4p = 0;
        float sq0 = 0.f, sq1 = 0.f;
        int mc = 0;

#pragma unroll 8
        for (int k = tid; k < CHUNKS; k += THREADS) {
            float4 v = xb4[k];
            u64 plo = pk2(v.x, v.y), phi = pk2(v.z, v.w);
            s2p = fma2(plo, plo, s2p);
            s2p = fma2(phi, phi, s2p);
            u64 alo = plo & ABSM, ahi = phi & ABSM;
            sap = add2(sap, add2(alo, ahi));
            float b0, b1, b2, b3;
            up2(alo, b0, b1); up2(ahi, b2, b3);
            sq0 += sqrt_approx(b0) + sqrt_approx(b1);
            sq1 += sqrt_approx(b2) + sqrt_approx(b3);
            u64 dlo = add2(plo, nmB), dhi = add2(phi, nmB);
            u64 tlo = mul2(dlo, dlo), thi = mul2(dhi, dhi);
            d2p = add2(d2p, add2(tlo, thi));
            d3p = fma2(tlo, dlo, d3p);
            d3p = fma2(thi, dhi, d3p);
            d4p = fma2(tlo, tlo, d4p);
            d4p = fma2(thi, thi, d4p);
            float d0, d1, d2v, d3v;
            up2(dlo, d0, d1); up2(dhi, d2v, d3v);
            unsigned c0 = __float_as_uint(d0), c1 = __float_as_uint(d1);
            unsigned c2 = __float_as_uint(d2v), c3 = __float_as_uint(d3v);
            unsigned nc0 = __shfl_down_sync(0xffffffffu, c0, 1);
            mc += (int)(((c0 ^ c1) >> 31) + ((c1 ^ c2) >> 31) + ((c2 ^ c3) >> 31)
                        + (((c3 ^ nc0) >> 31) & vmask));
        }

        // rowB cleanup: 511 warp-span boundary pairs
        int zceB = 0;
        if (tid < 511) {
            float a = __ldg(xb + 128 * tid + 127);
            float b = __ldg(xb + 128 * tid + 128);
            zceB = (int)((__float_as_uint(a) ^ __float_as_uint(b)) >> 31);
            float ca = a - meanB, cb = b - meanB;
            mc += (int)((__float_as_uint(ca) ^ __float_as_uint(cb)) >> 31);
        }

        float s2 = hsum2(s2p), sa = hsum2(sap), sqv = sq0 + sq1;
        float d2 = hsum2(d2p), d3 = hsum2(d3p), d4 = hsum2(d4p);
        s2 = warp_sum(s2); sa = warp_sum(sa); sqv = warp_sum(sqv);
        d2 = warp_sum(d2); d3 = warp_sum(d3); d4 = warp_sum(d4);
        mc = warp_sumi(mc); zceB = warp_sumi(zceB);
        if (lane == 0) {
            w_f[0][wid] = s2; w_f[1][wid] = sa; w_f[2][wid] = sqv;
            w_f[3][wid] = d2; w_f[4][wid] = d3; w_f[5][wid] = d4;
            w_k[0][wid] = mc; w_k[1][wid] = zceB;
        }
    }
    __syncthreads();
    if (tid == 0) {
        double S2 = 0, Sa = 0, Sq = 0, D2 = 0, D3 = 0, D4 = 0;
        int rmc = 0, rzceB = 0;
        for (int i = 0; i < NWARP; i++) {
            S2 += (double)w_f[0][i]; Sa += (double)w_f[1][i]; Sq += (double)w_f[2][i];
            D2 += (double)w_f[3][i]; D3 += (double)w_f[4][i]; D4 += (double)w_f[5][i];
            rmc += w_k[0][i]; rzceB += w_k[1][i];
        }
        finalize_row(out + (size_t)rowB * 17,
                     sB_S1, S2, Sa, Sq, (double)sB_pk, (double)sB_pkn,
                     sB_zc + rzceB, rmc, D2, D3, D4);
    }
}

extern "C" void kernel_launch(void* const* d_in, const int* in_sizes, int n_in,
                              void* d_out, int out_size) {
    const float* x = (const float*)d_in[0];
    float* out = (float*)d_out;
    int rows = in_sizes[0] / TLEN;   // 1024
    stat_feat_kernel<<<rows / 2, THREADS>>>(x, out);
}